// round 16
// baseline (speedup 1.0000x reference)
#include <cuda_runtime.h>
#include <cuda_fp16.h>
#include <cstdint>

#define HH 128
#define WW 128
#define CC 392
#define KPOOL 7
#define KK 49
#define MAXN 2048

#define CPAD 416              // channels padded (13 x 32)
#define PFW 130               // padded spatial (halo 1)
#define KTOT (9 * CPAD)       // 3744
#define NCH 117               // 9 taps * 13 ci-blocks of 32

#define PFAREA (PFW * PFW * CPAD)
#define WTAREA (CC * KTOT)

#define NTILES 896            // 128 M-tiles (rows) x 7 N-tiles (56)
#define GRID 444              // 148 SMs x 3 CTAs

#define LO_SCALE 256.0f
#define LO_INV   (1.0f / 256.0f)

// smem per stage (bytes): A_hi[128*64] A_lo[128*64] B_hi[56*64] B_lo[56*64]
#define ST_AHI 0
#define ST_ALO 8192
#define ST_BHI 16384
#define ST_BLO 19968
#define STAGE_BYTES 23552
#define SMEM_BYTES (3 * STAGE_BYTES)

// ---------------------------------------------------------------------------
// Device scratch (no allocation allowed). hi matrix at [0], lo (x256) at [AREA].
// ---------------------------------------------------------------------------
__device__ __half g_pf[2 * PFAREA];
__device__ __half g_wt[2 * WTAREA];
__device__ float g_map[HH * WW * CC];
__device__ float g_off[MAXN * KK * 8];

// ---------------------------------------------------------------------------
// PTX helpers (baseline sm_80-era — safe for compute_103)
// ---------------------------------------------------------------------------
__device__ __forceinline__ uint32_t smem_u32(const void* p) {
    uint32_t a;
    asm("{ .reg .u64 t; cvta.to.shared.u64 t, %1; cvt.u32.u64 %0, t; }" : "=r"(a) : "l"(p));
    return a;
}
#define CP16(dst, src) \
    asm volatile("cp.async.cg.shared.global [%0], [%1], 16;" :: "r"(dst), "l"(src))
#define CP_COMMIT() asm volatile("cp.async.commit_group;" ::: "memory")
#define CP_WAIT2() asm volatile("cp.async.wait_group 2;" ::: "memory")
#define CP_WAIT1() asm volatile("cp.async.wait_group 1;" ::: "memory")
#define CP_WAIT0() asm volatile("cp.async.wait_group 0;" ::: "memory")

#define LDSM4(r, a) \
    asm volatile("ldmatrix.sync.aligned.m8n8.x4.shared.b16 {%0,%1,%2,%3}, [%4];" \
        : "=r"((r)[0]), "=r"((r)[1]), "=r"((r)[2]), "=r"((r)[3]) : "r"(a))
#define LDSM2(r0, r1, a) \
    asm volatile("ldmatrix.sync.aligned.m8n8.x2.shared.b16 {%0,%1}, [%2];" \
        : "=r"(r0), "=r"(r1) : "r"(a))

// f32-accumulate fp16 MMA (hh pass)
#define MMA32(ar, b0, b1, cc) \
    asm volatile("mma.sync.aligned.m16n8k16.row.col.f32.f16.f16.f32 " \
        "{%0,%1,%2,%3}, {%4,%5,%6,%7}, {%8,%9}, {%0,%1,%2,%3};" \
        : "+f"((cc)[0]), "+f"((cc)[1]), "+f"((cc)[2]), "+f"((cc)[3]) \
        : "r"((ar)[0]), "r"((ar)[1]), "r"((ar)[2]), "r"((ar)[3]), "r"(b0), "r"(b1))

// f16-accumulate fp16 MMA (lo passes) — acc is 2 regs of f16x2
#define MMA16(ar, b0, b1, cc) \
    asm volatile("mma.sync.aligned.m16n8k16.row.col.f16.f16.f16.f16 " \
        "{%0,%1}, {%2,%3,%4,%5}, {%6,%7}, {%0,%1};" \
        : "+r"((cc)[0]), "+r"((cc)[1]) \
        : "r"((ar)[0]), "r"((ar)[1]), "r"((ar)[2]), "r"((ar)[3]), "r"(b0), "r"(b1))

#define PASS32(A, B) do { \
    MMA32((A), (B)[0], (B)[2],  acc[0]); MMA32((A), (B)[1], (B)[3],  acc[1]); \
    MMA32((A), (B)[4], (B)[6],  acc[2]); MMA32((A), (B)[5], (B)[7],  acc[3]); \
    MMA32((A), (B)[8], (B)[10], acc[4]); MMA32((A), (B)[9], (B)[11], acc[5]); \
    MMA32((A), (B)[12], (B)[13], acc[6]); \
} while (0)

#define PASS16(A, B) do { \
    MMA16((A), (B)[0], (B)[2],  accp[0]); MMA16((A), (B)[1], (B)[3],  accp[1]); \
    MMA16((A), (B)[4], (B)[6],  accp[2]); MMA16((A), (B)[5], (B)[7],  accp[3]); \
    MMA16((A), (B)[8], (B)[10], accp[4]); MMA16((A), (B)[9], (B)[11], accp[5]); \
    MMA16((A), (B)[12], (B)[13], accp[6]); \
} while (0)

// swizzled smem offset: 64B rows, seg = 16B column (0..3)
__device__ __forceinline__ uint32_t swz(int row, int seg) {
    return (uint32_t)(row * 64 + ((seg ^ ((row >> 1) & 3)) << 4));
}

// fp16 hi/lo split: v = hi + lo/256 (lo stored x256, exact in fp16)
__device__ __forceinline__ void split16(float v, uint16_t& h, uint16_t& l) {
    __half hb = __float2half(v);
    float r = (v - __half2float(hb)) * LO_SCALE;
    h = __half_as_ushort(hb);
    l = __half_as_ushort(__float2half(r));
}

// ---------------------------------------------------------------------------
// Precompute 1: pad + split features -> g_pf [2][130,130,416]
// ---------------------------------------------------------------------------
__global__ __launch_bounds__(256) void pad_split_features(const float* __restrict__ f)
{
    int idx = blockIdx.x * 256 + threadIdx.x;
    const int TOT = PFW * PFW * (CPAD / 4);
    if (idx >= TOT) return;
    int p = idx / (CPAD / 4);
    int c0 = (idx - p * (CPAD / 4)) * 4;
    int y = p / PFW - 1;
    int x = p - (y + 1) * PFW - 1;
    bool in = ((unsigned)y < HH) && ((unsigned)x < WW);
    uint16_t h[4], l[4];
#pragma unroll
    for (int j = 0; j < 4; ++j) {
        int c = c0 + j;
        float v = (in && c < CC) ? __ldg(f + ((size_t)(y * WW + x)) * CC + c) : 0.f;
        split16(v, h[j], l[j]);
    }
    size_t o = (size_t)p * CPAD + c0;
    *(uint2*)(g_pf + o) = make_uint2((uint32_t)h[0] | ((uint32_t)h[1] << 16),
                                     (uint32_t)h[2] | ((uint32_t)h[3] << 16));
    *(uint2*)(g_pf + PFAREA + o) = make_uint2((uint32_t)l[0] | ((uint32_t)l[1] << 16),
                                              (uint32_t)l[2] | ((uint32_t)l[3] << 16));
}

// ---------------------------------------------------------------------------
// Precompute 2: coalesced transpose + split weights -> g_wt [2][392][3744]
// ---------------------------------------------------------------------------
__global__ __launch_bounds__(256) void split_weights(const float* __restrict__ w)
{
    __shared__ float tile[32][33];
    const int tap = blockIdx.z;
    const int ci0 = blockIdx.x * 32;
    const int n0  = blockIdx.y * 32;
    const int tx = threadIdx.x & 31;
    const int ty = threadIdx.x >> 5;
#pragma unroll
    for (int r = 0; r < 4; ++r) {
        int ci = ci0 + ty + r * 8;
        int n  = n0 + tx;
        float v = 0.f;
        if (ci < CC && n < CC) v = __ldg(w + ((size_t)(tap * CC + ci)) * CC + n);
        tile[ty + r * 8][tx] = v;
    }
    __syncthreads();
#pragma unroll
    for (int r = 0; r < 4; ++r) {
        int n  = n0 + ty + r * 8;
        int ci = ci0 + tx;
        if (n < CC && ci < CPAD) {
            float v = (ci < CC) ? tile[tx][ty + r * 8] : 0.f;
            uint16_t h, l;
            split16(v, h, l);
            size_t o = (size_t)n * KTOT + tap * CPAD + ci;
            g_wt[o] = __ushort_as_half(h);
            g_wt[WTAREA + o] = __ushort_as_half(l);
        }
    }
}

__global__ __launch_bounds__(256) void pad_weights_tail()
{
    int idx = blockIdx.x * 256 + threadIdx.x;
    const int TOT = CC * 9 * (CPAD - CC);
    if (idx >= TOT) return;
    int n = idx / (9 * (CPAD - CC));
    int rem = idx - n * 9 * (CPAD - CC);
    int tap = rem / (CPAD - CC);
    int ci = CC + rem - tap * (CPAD - CC);
    size_t o = (size_t)n * KTOT + tap * CPAD + ci;
    g_wt[o] = __float2half(0.f);
    g_wt[WTAREA + o] = __float2half(0.f);
}

// ---------------------------------------------------------------------------
// Conv implicit GEMM, persistent. Tile: BM=128 (1 row), BN=56. 256 threads,
// 8 warps on M (warp tile 16x56). fp16 split: hh pass in f32-acc, lh+hl in
// shared f16-acc (x256 scale, combined in epilogue). 3-stage cp.async,
// 3 CTAs/SM, hoisted addressing.
// ---------------------------------------------------------------------------
__global__ void __launch_bounds__(256, 3) conv_mma_kernel()
{
    extern __shared__ char smem[];
    uint32_t sm = smem_u32(smem);
    const int tid  = threadIdx.x;
    const int lane = tid & 31;
    const int wid  = tid >> 5;

    const int l15 = lane & 15;
    const int l7  = lane & 7;
    const int hi16 = lane >> 4;
    const int hi8  = (lane >> 3) & 1;
    const int arow = wid * 16 + l15;

    // ---- per-thread cp.async constants ----
    int aoff_e[4]; uint32_t adst[4];
#pragma unroll
    for (int t = 0; t < 4; ++t) {
        int i = tid + t * 256;
        int mat = i >> 9;
        int r = (i >> 2) & 127;
        int seg = i & 3;
        aoff_e[t] = mat * PFAREA + r * CPAD + seg * 8;
        adst[t] = (uint32_t)(mat * 8192) + swz(r, seg);
    }
    int boff_e[2]; uint32_t bdst[2];
#pragma unroll
    for (int t = 0; t < 2; ++t) {
        int i = tid + t * 256;
        int mat = (i >= 224);
        int ii = i - mat * 224;
        int rr = ii >> 2;
        int seg = ii & 3;
        boff_e[t] = mat * WTAREA + rr * KTOT + seg * 8;
        bdst[t] = (uint32_t)(ST_BHI + mat * 3584) + swz(rr, seg);
    }
    const bool bact1 = (tid < 192);

    // ---- per-thread LDSM offsets (per ks) ----
    uint32_t aof[2], bof0[2], bof1[2], bof2[2], bof3[2];
#pragma unroll
    for (int ks = 0; ks < 2; ++ks) {
        int sa = ks * 2 + hi16;
        int s2 = ks * 2 + hi8;
        aof[ks]  = ST_AHI + swz(arow, sa);
        bof0[ks] = ST_BHI + swz(l15, sa);
        bof1[ks] = ST_BHI + swz(16 + l15, sa);
        bof2[ks] = ST_BHI + swz(32 + l15, sa);
        bof3[ks] = ST_BHI + swz(48 + l7, s2);
    }

#define ISSUE_CHUNK(sidx) do {                                                \
    uint32_t sb = sm + (sidx) * STAGE_BYTES;                                  \
    CP16(sb + adst[0], g_pf + (size_t)(au + aoff_e[0]));                      \
    CP16(sb + adst[1], g_pf + (size_t)(au + aoff_e[1]));                      \
    CP16(sb + adst[2], g_pf + (size_t)(au + aoff_e[2]));                      \
    CP16(sb + adst[3], g_pf + (size_t)(au + aoff_e[3]));                      \
    CP16(sb + bdst[0], g_wt + (size_t)(bu + boff_e[0]));                      \
    if (bact1) CP16(sb + bdst[1], g_wt + (size_t)(bu + boff_e[1]));           \
    CP_COMMIT();                                                              \
    if (++pf_ci == 13) {                                                      \
        pf_ci = 0; ++pf_tap;                                                  \
        int dyv = pf_tap / 3 - 1;                                             \
        int dxv = pf_tap - (pf_tap / 3) * 3 - 1;                              \
        au = ((y + dyv + 1) * PFW + (dxv + 1)) * CPAD;                        \
        bu = n0 * KTOT + pf_tap * CPAD;                                       \
    } else { au += 32; bu += 32; }                                            \
} while (0)

#pragma unroll 1
    for (int tt = blockIdx.x; tt < NTILES; tt += GRID) {
        const int y  = tt / 7;
        const int n0 = (tt - y * 7) * 56;

        float acc[7][4];
        uint32_t accp[7][2];
#pragma unroll
        for (int j = 0; j < 7; ++j) {
#pragma unroll
            for (int q = 0; q < 4; ++q) acc[j][q] = 0.f;
            accp[j][0] = 0u; accp[j][1] = 0u;
        }

        int pf_tap = 0, pf_ci = 0;
        int au = (y * PFW) * CPAD;
        int bu = n0 * KTOT;

        ISSUE_CHUNK(0);
        ISSUE_CHUNK(1);
        ISSUE_CHUNK(2);

        int s = 0;
#pragma unroll 1
        for (int c = 0; c < NCH; ++c) {
            if (c < NCH - 2)       { CP_WAIT2(); }
            else if (c == NCH - 2) { CP_WAIT1(); }
            else                   { CP_WAIT0(); }
            __syncthreads();
            const uint32_t st = sm + s * STAGE_BYTES;
#pragma unroll
            for (int ks = 0; ks < 2; ++ks) {
                uint32_t ah[4], aw[4], bh[14], bl[14];
                const uint32_t a_hi = st + aof[ks];
                LDSM4(ah, a_hi);
                LDSM4(&bh[0], st + bof0[ks]);
                LDSM4(&bh[4], st + bof1[ks]);
                LDSM4(&bh[8], st + bof2[ks]);
                LDSM2(bh[12], bh[13], st + bof3[ks]);
                PASS32(ah, bh);                     // hi * hi (f32 acc)
                LDSM4(aw, a_hi + (ST_ALO - ST_AHI));
                PASS16(aw, bh);                     // lo * hi (f16 acc)
                LDSM4(&bl[0], st + bof0[ks] + (ST_BLO - ST_BHI));
                LDSM4(&bl[4], st + bof1[ks] + (ST_BLO - ST_BHI));
                LDSM4(&bl[8], st + bof2[ks] + (ST_BLO - ST_BHI));
                LDSM2(bl[12], bl[13], st + bof3[ks] + (ST_BLO - ST_BHI));
                PASS16(ah, bl);                     // hi * lo (f16 acc)
            }
            __syncthreads();
            if (c + 3 < NCH) ISSUE_CHUNK(s);
            s = (s == 2) ? 0 : s + 1;
        }

        // epilogue: combine hi acc + lo acc (x256) -> g_map[y, x, n]
        {
            const int nlane = n0 + (lane & 3) * 2;
#pragma unroll
            for (int j = 0; j < 7; ++j) {
                float2 p0 = __half22float2(*(__half2*)&accp[j][0]);
                float2 p1 = __half22float2(*(__half2*)&accp[j][1]);
                acc[j][0] += p0.x * LO_INV;
                acc[j][1] += p0.y * LO_INV;
                acc[j][2] += p1.x * LO_INV;
                acc[j][3] += p1.y * LO_INV;
            }
#pragma unroll
            for (int h = 0; h < 2; ++h) {
                const int x = wid * 16 + (lane >> 2) + h * 8;
                float* op = g_map + ((size_t)(y * WW + x)) * CC;
#pragma unroll
                for (int j = 0; j < 7; ++j)
                    *(float2*)(op + nlane + j * 8) =
                        make_float2(acc[j][h * 2], acc[j][h * 2 + 1]);
            }
        }
    }
#undef ISSUE_CHUNK
}

// ---------------------------------------------------------------------------
// Kernel: PS-RoI pool of conv map -> per-bin offsets (feature coords)
// ---------------------------------------------------------------------------
__global__ __launch_bounds__(256) void offset_pool_kernel(const float* __restrict__ rois, int N)
{
    int idx = blockIdx.x * blockDim.x + threadIdx.x;
    if (idx >= N * KK) return;
    int n   = idx / KK;
    int bin = idx - n * KK;
    int bi  = bin / KPOOL;
    int bj  = bin - bi * KPOOL;

    const float* r = rois + n * 5;
    float r1 = r[1], r2 = r[2], r3 = r[3], r4 = r[4];
    float x1 = r1 * 0.0625f;
    float y1 = r2 * 0.0625f;
    float x2 = (r3 + 1.0f) * 0.0625f;
    float y2 = (r4 + 1.0f) * 0.0625f;
    float bw = (x2 - x1) / 7.0f;
    float bh = (y2 - y1) / 7.0f;
    float cx = x1 + ((float)bj + 0.5f) * bw;
    float cy = y1 + ((float)bi + 0.5f) * bh;

    float y0f = floorf(cy), x0f = floorf(cx);
    float wy = cy - y0f,    wx = cx - x0f;
    int iy0 = min(max((int)y0f, 0), HH - 1);
    int iy1 = min(max((int)y0f + 1, 0), HH - 1);
    int ix0 = min(max((int)x0f, 0), WW - 1);
    int ix1 = min(max((int)x0f + 1, 0), WW - 1);

    float w00 = (1.f - wy) * (1.f - wx);
    float w01 = (1.f - wy) * wx;
    float w10 = wy * (1.f - wx);
    float w11 = wy * wx;

    const float* p00 = g_map + ((size_t)(iy0 * WW + ix0)) * CC + bin * 8;
    const float* p01 = g_map + ((size_t)(iy0 * WW + ix1)) * CC + bin * 8;
    const float* p10 = g_map + ((size_t)(iy1 * WW + ix0)) * CC + bin * 8;
    const float* p11 = g_map + ((size_t)(iy1 * WW + ix1)) * CC + bin * 8;

    float rw = r3 - r1 + 1.0f;
    float rh = r4 - r2 + 1.0f;

    float* o = g_off + (size_t)idx * 8;
#pragma unroll
    for (int g = 0; g < 4; ++g) {
        int d0 = g * 2, d1 = g * 2 + 1;
        float px = w00 * p00[d0] + w01 * p01[d0] + w10 * p10[d0] + w11 * p11[d0];
        float py = w00 * p00[d1] + w01 * p01[d1] + w10 * p10[d1] + w11 * p11[d1];
        o[d0] = (px * rw) * 0.1f * 0.0625f;
        o[d1] = (py * rh) * 0.1f * 0.0625f;
    }
}

// ---------------------------------------------------------------------------
// Kernel: deformable PS-RoI pool of raw features -> output [N,8,7,7]
// ---------------------------------------------------------------------------
__global__ __launch_bounds__(256) void deform_pool_kernel(const float* __restrict__ f,
                                                          const float* __restrict__ rois,
                                                          float* __restrict__ out, int N)
{
    int idx = blockIdx.x * blockDim.x + threadIdx.x;
    if (idx >= N * KK * 8) return;
    int d   = idx & 7;
    int nb  = idx >> 3;
    int n   = nb / KK;
    int bin = nb - n * KK;
    int bi  = bin / KPOOL;
    int bj  = bin - bi * KPOOL;

    const float* r = rois + n * 5;
    float x1 = r[1] * 0.0625f;
    float y1 = r[2] * 0.0625f;
    float x2 = (r[3] + 1.0f) * 0.0625f;
    float y2 = (r[4] + 1.0f) * 0.0625f;
    float bw = (x2 - x1) / 7.0f;
    float bh = (y2 - y1) / 7.0f;
    float cx = x1 + ((float)bj + 0.5f) * bw;
    float cy = y1 + ((float)bi + 0.5f) * bh;

    int g = d >> 1;
    const float* o = g_off + (size_t)nb * 8 + g * 2;
    float sx = cx + o[0];
    float sy = cy + o[1];

    float y0f = floorf(sy), x0f = floorf(sx);
    float wy = sy - y0f,    wx = sx - x0f;
    int iy0 = min(max((int)y0f, 0), HH - 1);
    int iy1 = min(max((int)y0f + 1, 0), HH - 1);
    int ix0 = min(max((int)x0f, 0), WW - 1);
    int ix1 = min(max((int)x0f + 1, 0), WW - 1);

    int ch = bin * 8 + d;
    float v00 = __ldg(f + ((size_t)(iy0 * WW + ix0)) * CC + ch);
    float v01 = __ldg(f + ((size_t)(iy0 * WW + ix1)) * CC + ch);
    float v10 = __ldg(f + ((size_t)(iy1 * WW + ix0)) * CC + ch);
    float v11 = __ldg(f + ((size_t)(iy1 * WW + ix1)) * CC + ch);

    float val = (1.f - wy) * (1.f - wx) * v00 + (1.f - wy) * wx * v01
              + wy * (1.f - wx) * v10 + wy * wx * v11;

    out[((size_t)n * 8 + d) * KK + bin] = val;
}

// ---------------------------------------------------------------------------
extern "C" void kernel_launch(void* const* d_in, const int* in_sizes, int n_in,
                              void* d_out, int out_size)
{
    const float* features = (const float*)d_in[0];  // [1,128,128,392]
    const float* rois     = (const float*)d_in[1];  // [N,5]
    const float* conv_w   = (const float*)d_in[2];  // [3,3,392,392]
    float* out = (float*)d_out;
    int N = in_sizes[1] / 5;

    cudaFuncSetAttribute(conv_mma_kernel, cudaFuncAttributeMaxDynamicSharedMemorySize, SMEM_BYTES);

    {
        int tot = PFW * PFW * (CPAD / 4);
        pad_split_features<<<(tot + 255) / 256, 256>>>(features);
        dim3 gw(13, 13, 9);
        split_weights<<<gw, 256>>>(conv_w);
        int pt = CC * 9 * (CPAD - CC);
        pad_weights_tail<<<(pt + 255) / 256, 256>>>();
    }

    conv_mma_kernel<<<GRID, 256, SMEM_BYTES>>>();

    int t2 = N * KK;
    offset_pool_kernel<<<(t2 + 255) / 256, 256>>>(rois, N);

    int t3 = N * KK * 8;
    deform_pool_kernel<<<(t3 + 255) / 256, 256>>>(features, rois, out, N);
}

// round 17
// speedup vs baseline: 1.3677x; 1.3677x over previous
#include <cuda_runtime.h>
#include <cuda_fp16.h>
#include <cstdint>

#define HH 128
#define WW 128
#define CC 392
#define KPOOL 7
#define KK 49
#define MAXN 2048

#define CPAD 416              // channels padded (13 x 32)
#define PFW 130               // padded spatial (halo 1)
#define KTOT (9 * CPAD)       // 3744
#define NCH 117               // 9 taps * 13 ci-blocks of 32

#define PFAREA (PFW * PFW * CPAD)
#define WTAREA (CC * KTOT)

#define NTILES 896            // 128 M-tiles (rows) x 7 N-tiles (56)
#define GRID 444              // 148 SMs x 3 CTAs

// smem per stage (bytes): A_hi[128*64] A_lo[128*64] B[56*64]
#define ST_AHI 0
#define ST_ALO 8192
#define ST_B   16384
#define STAGE_BYTES 19968
#define SMEM_BYTES (3 * STAGE_BYTES)

// ---------------------------------------------------------------------------
// Device scratch (no allocation allowed). Features: hi at [0], lo at [PFAREA].
// Weights: single fp16 matrix.
// ---------------------------------------------------------------------------
__device__ __half g_pf[2 * PFAREA];
__device__ __half g_wt[WTAREA];
__device__ float g_map[HH * WW * CC];
__device__ float g_off[MAXN * KK * 8];

// ---------------------------------------------------------------------------
// PTX helpers (baseline sm_80-era — safe for compute_103)
// ---------------------------------------------------------------------------
__device__ __forceinline__ uint32_t smem_u32(const void* p) {
    uint32_t a;
    asm("{ .reg .u64 t; cvta.to.shared.u64 t, %1; cvt.u32.u64 %0, t; }" : "=r"(a) : "l"(p));
    return a;
}
#define CP16(dst, src) \
    asm volatile("cp.async.cg.shared.global [%0], [%1], 16;" :: "r"(dst), "l"(src))
#define CP_COMMIT() asm volatile("cp.async.commit_group;" ::: "memory")
#define CP_WAIT2() asm volatile("cp.async.wait_group 2;" ::: "memory")
#define CP_WAIT1() asm volatile("cp.async.wait_group 1;" ::: "memory")
#define CP_WAIT0() asm volatile("cp.async.wait_group 0;" ::: "memory")

#define LDSM4(r, a) \
    asm volatile("ldmatrix.sync.aligned.m8n8.x4.shared.b16 {%0,%1,%2,%3}, [%4];" \
        : "=r"((r)[0]), "=r"((r)[1]), "=r"((r)[2]), "=r"((r)[3]) : "r"(a))
#define LDSM2(r0, r1, a) \
    asm volatile("ldmatrix.sync.aligned.m8n8.x2.shared.b16 {%0,%1}, [%2];" \
        : "=r"(r0), "=r"(r1) : "r"(a))

#define MMA(ar, b0, b1, cc) \
    asm volatile("mma.sync.aligned.m16n8k16.row.col.f32.f16.f16.f32 " \
        "{%0,%1,%2,%3}, {%4,%5,%6,%7}, {%8,%9}, {%0,%1,%2,%3};" \
        : "+f"((cc)[0]), "+f"((cc)[1]), "+f"((cc)[2]), "+f"((cc)[3]) \
        : "r"((ar)[0]), "r"((ar)[1]), "r"((ar)[2]), "r"((ar)[3]), "r"(b0), "r"(b1))

// one A frag (m16) x 7 n8 frags, shared f32 accumulator
#define PASS(A, B) do { \
    MMA((A), (B)[0], (B)[2],  acc[0]); MMA((A), (B)[1], (B)[3],  acc[1]); \
    MMA((A), (B)[4], (B)[6],  acc[2]); MMA((A), (B)[5], (B)[7],  acc[3]); \
    MMA((A), (B)[8], (B)[10], acc[4]); MMA((A), (B)[9], (B)[11], acc[5]); \
    MMA((A), (B)[12], (B)[13], acc[6]); \
} while (0)

// swizzled smem offset: 64B rows, seg = 16B column (0..3)
__device__ __forceinline__ uint32_t swz(int row, int seg) {
    return (uint32_t)(row * 64 + ((seg ^ ((row >> 1) & 3)) << 4));
}

// exact fp16 hi/lo split of fp32: v = hi + lo (lo unscaled; residual ~2^-24)
__device__ __forceinline__ void split16(float v, uint16_t& h, uint16_t& l) {
    __half hb = __float2half(v);
    float r = v - __half2float(hb);
    h = __half_as_ushort(hb);
    l = __half_as_ushort(__float2half(r));
}

// ---------------------------------------------------------------------------
// Precompute 1: pad + split features -> g_pf [2][130,130,416]
// ---------------------------------------------------------------------------
__global__ __launch_bounds__(256) void pad_split_features(const float* __restrict__ f)
{
    int idx = blockIdx.x * 256 + threadIdx.x;
    const int TOT = PFW * PFW * (CPAD / 4);
    if (idx >= TOT) return;
    int p = idx / (CPAD / 4);
    int c0 = (idx - p * (CPAD / 4)) * 4;
    int y = p / PFW - 1;
    int x = p - (y + 1) * PFW - 1;
    bool in = ((unsigned)y < HH) && ((unsigned)x < WW);
    uint16_t h[4], l[4];
#pragma unroll
    for (int j = 0; j < 4; ++j) {
        int c = c0 + j;
        float v = (in && c < CC) ? __ldg(f + ((size_t)(y * WW + x)) * CC + c) : 0.f;
        split16(v, h[j], l[j]);
    }
    size_t o = (size_t)p * CPAD + c0;
    *(uint2*)(g_pf + o) = make_uint2((uint32_t)h[0] | ((uint32_t)h[1] << 16),
                                     (uint32_t)h[2] | ((uint32_t)h[3] << 16));
    *(uint2*)(g_pf + PFAREA + o) = make_uint2((uint32_t)l[0] | ((uint32_t)l[1] << 16),
                                              (uint32_t)l[2] | ((uint32_t)l[3] << 16));
}

// ---------------------------------------------------------------------------
// Precompute 2: coalesced transpose weights -> g_wt [392][3744] (single fp16)
// ---------------------------------------------------------------------------
__global__ __launch_bounds__(256) void split_weights(const float* __restrict__ w)
{
    __shared__ float tile[32][33];
    const int tap = blockIdx.z;
    const int ci0 = blockIdx.x * 32;
    const int n0  = blockIdx.y * 32;
    const int tx = threadIdx.x & 31;
    const int ty = threadIdx.x >> 5;
#pragma unroll
    for (int r = 0; r < 4; ++r) {
        int ci = ci0 + ty + r * 8;
        int n  = n0 + tx;
        float v = 0.f;
        if (ci < CC && n < CC) v = __ldg(w + ((size_t)(tap * CC + ci)) * CC + n);
        tile[ty + r * 8][tx] = v;
    }
    __syncthreads();
#pragma unroll
    for (int r = 0; r < 4; ++r) {
        int n  = n0 + ty + r * 8;
        int ci = ci0 + tx;
        if (n < CC && ci < CPAD) {
            float v = (ci < CC) ? tile[tx][ty + r * 8] : 0.f;
            g_wt[(size_t)n * KTOT + tap * CPAD + ci] = __float2half(v);
        }
    }
}

__global__ __launch_bounds__(256) void pad_weights_tail()
{
    int idx = blockIdx.x * 256 + threadIdx.x;
    const int TOT = CC * 9 * (CPAD - CC);
    if (idx >= TOT) return;
    int n = idx / (9 * (CPAD - CC));
    int rem = idx - n * 9 * (CPAD - CC);
    int tap = rem / (CPAD - CC);
    int ci = CC + rem - tap * (CPAD - CC);
    g_wt[(size_t)n * KTOT + tap * CPAD + ci] = __float2half(0.f);
}

// ---------------------------------------------------------------------------
// Conv implicit GEMM, persistent. Tile: BM=128 (1 row), BN=56. 256 threads,
// 8 warps on M (warp tile 16x56). 2-pass fp16 split: (ah + al) x wh, both
// f32-acc into one shared accumulator. 3-stage cp.async, 3 CTAs/SM,
// hoisted addressing. 28 MMAs/chunk/warp (was 42).
// ---------------------------------------------------------------------------
__global__ void __launch_bounds__(256, 3) conv_mma_kernel()
{
    extern __shared__ char smem[];
    uint32_t sm = smem_u32(smem);
    const int tid  = threadIdx.x;
    const int lane = tid & 31;
    const int wid  = tid >> 5;

    const int l15 = lane & 15;
    const int l7  = lane & 7;
    const int hi16 = lane >> 4;
    const int hi8  = (lane >> 3) & 1;
    const int arow = wid * 16 + l15;

    // ---- per-thread cp.async constants ----
    // A: 2 mats x 128 rows x 4 segs = 1024 16B-ops over 256 threads (4 each)
    int aoff_e[4]; uint32_t adst[4];
#pragma unroll
    for (int t = 0; t < 4; ++t) {
        int i = tid + t * 256;
        int mat = i >> 9;
        int r = (i >> 2) & 127;
        int seg = i & 3;
        aoff_e[t] = mat * PFAREA + r * CPAD + seg * 8;
        adst[t] = (uint32_t)(mat * 8192) + swz(r, seg);
    }
    // B: 56 rows x 4 segs = 224 ops; threads 0..223
    int boff_e = 0; uint32_t bdst = 0;
    const bool bact = (tid < 224);
    {
        int rr = tid >> 2;
        int seg = tid & 3;
        boff_e = rr * KTOT + seg * 8;
        bdst = (uint32_t)ST_B + swz(rr, seg);
    }

    // ---- per-thread LDSM offsets (per ks) ----
    uint32_t aof[2], bof0[2], bof1[2], bof2[2], bof3[2];
#pragma unroll
    for (int ks = 0; ks < 2; ++ks) {
        int sa = ks * 2 + hi16;
        int s2 = ks * 2 + hi8;
        aof[ks]  = ST_AHI + swz(arow, sa);
        bof0[ks] = ST_B + swz(l15, sa);
        bof1[ks] = ST_B + swz(16 + l15, sa);
        bof2[ks] = ST_B + swz(32 + l15, sa);
        bof3[ks] = ST_B + swz(48 + l7, s2);
    }

#define ISSUE_CHUNK(sidx) do {                                                \
    uint32_t sb = sm + (sidx) * STAGE_BYTES;                                  \
    CP16(sb + adst[0], g_pf + (size_t)(au + aoff_e[0]));                      \
    CP16(sb + adst[1], g_pf + (size_t)(au + aoff_e[1]));                      \
    CP16(sb + adst[2], g_pf + (size_t)(au + aoff_e[2]));                      \
    CP16(sb + adst[3], g_pf + (size_t)(au + aoff_e[3]));                      \
    if (bact) CP16(sb + bdst, g_wt + (size_t)(bu + boff_e));                  \
    CP_COMMIT();                                                              \
    if (++pf_ci == 13) {                                                      \
        pf_ci = 0; ++pf_tap;                                                  \
        int dyv = pf_tap / 3 - 1;                                             \
        int dxv = pf_tap - (pf_tap / 3) * 3 - 1;                              \
        au = ((y + dyv + 1) * PFW + (dxv + 1)) * CPAD;                        \
        bu = n0 * KTOT + pf_tap * CPAD;                                       \
    } else { au += 32; bu += 32; }                                            \
} while (0)

#pragma unroll 1
    for (int tt = blockIdx.x; tt < NTILES; tt += GRID) {
        const int y  = tt / 7;
        const int n0 = (tt - y * 7) * 56;

        float acc[7][4];
#pragma unroll
        for (int j = 0; j < 7; ++j)
#pragma unroll
            for (int q = 0; q < 4; ++q) acc[j][q] = 0.f;

        int pf_tap = 0, pf_ci = 0;
        int au = (y * PFW) * CPAD;
        int bu = n0 * KTOT;

        ISSUE_CHUNK(0);
        ISSUE_CHUNK(1);
        ISSUE_CHUNK(2);

        int s = 0;
#pragma unroll 1
        for (int c = 0; c < NCH; ++c) {
            if (c < NCH - 2)       { CP_WAIT2(); }
            else if (c == NCH - 2) { CP_WAIT1(); }
            else                   { CP_WAIT0(); }
            __syncthreads();
            const uint32_t st = sm + s * STAGE_BYTES;
#pragma unroll
            for (int ks = 0; ks < 2; ++ks) {
                uint32_t ah[4], aw[4], bh[14];
                const uint32_t a_hi = st + aof[ks];
                LDSM4(ah, a_hi);
                LDSM4(&bh[0], st + bof0[ks]);
                LDSM4(&bh[4], st + bof1[ks]);
                LDSM4(&bh[8], st + bof2[ks]);
                LDSM2(bh[12], bh[13], st + bof3[ks]);
                PASS(ah, bh);                       // a_hi * w
                LDSM4(aw, a_hi + (ST_ALO - ST_AHI));
                PASS(aw, bh);                       // a_lo * w (same acc)
            }
            __syncthreads();
            if (c + 3 < NCH) ISSUE_CHUNK(s);
            s = (s == 2) ? 0 : s + 1;
        }

        // epilogue: warp tile 16x56 -> g_map[y, x, n]
        {
            const int nlane = n0 + (lane & 3) * 2;
#pragma unroll
            for (int h = 0; h < 2; ++h) {
                const int x = wid * 16 + (lane >> 2) + h * 8;
                float* op = g_map + ((size_t)(y * WW + x)) * CC;
#pragma unroll
                for (int j = 0; j < 7; ++j)
                    *(float2*)(op + nlane + j * 8) =
                        make_float2(acc[j][h * 2], acc[j][h * 2 + 1]);
            }
        }
    }
#undef ISSUE_CHUNK
}

// ---------------------------------------------------------------------------
// Kernel: PS-RoI pool of conv map -> per-bin offsets (feature coords)
// ---------------------------------------------------------------------------
__global__ __launch_bounds__(256) void offset_pool_kernel(const float* __restrict__ rois, int N)
{
    int idx = blockIdx.x * blockDim.x + threadIdx.x;
    if (idx >= N * KK) return;
    int n   = idx / KK;
    int bin = idx - n * KK;
    int bi  = bin / KPOOL;
    int bj  = bin - bi * KPOOL;

    const float* r = rois + n * 5;
    float r1 = r[1], r2 = r[2], r3 = r[3], r4 = r[4];
    float x1 = r1 * 0.0625f;
    float y1 = r2 * 0.0625f;
    float x2 = (r3 + 1.0f) * 0.0625f;
    float y2 = (r4 + 1.0f) * 0.0625f;
    float bw = (x2 - x1) / 7.0f;
    float bh = (y2 - y1) / 7.0f;
    float cx = x1 + ((float)bj + 0.5f) * bw;
    float cy = y1 + ((float)bi + 0.5f) * bh;

    float y0f = floorf(cy), x0f = floorf(cx);
    float wy = cy - y0f,    wx = cx - x0f;
    int iy0 = min(max((int)y0f, 0), HH - 1);
    int iy1 = min(max((int)y0f + 1, 0), HH - 1);
    int ix0 = min(max((int)x0f, 0), WW - 1);
    int ix1 = min(max((int)x0f + 1, 0), WW - 1);

    float w00 = (1.f - wy) * (1.f - wx);
    float w01 = (1.f - wy) * wx;
    float w10 = wy * (1.f - wx);
    float w11 = wy * wx;

    const float* p00 = g_map + ((size_t)(iy0 * WW + ix0)) * CC + bin * 8;
    const float* p01 = g_map + ((size_t)(iy0 * WW + ix1)) * CC + bin * 8;
    const float* p10 = g_map + ((size_t)(iy1 * WW + ix0)) * CC + bin * 8;
    const float* p11 = g_map + ((size_t)(iy1 * WW + ix1)) * CC + bin * 8;

    float rw = r3 - r1 + 1.0f;
    float rh = r4 - r2 + 1.0f;

    float* o = g_off + (size_t)idx * 8;
#pragma unroll
    for (int g = 0; g < 4; ++g) {
        int d0 = g * 2, d1 = g * 2 + 1;
        float px = w00 * p00[d0] + w01 * p01[d0] + w10 * p10[d0] + w11 * p11[d0];
        float py = w00 * p00[d1] + w01 * p01[d1] + w10 * p10[d1] + w11 * p11[d1];
        o[d0] = (px * rw) * 0.1f * 0.0625f;
        o[d1] = (py * rh) * 0.1f * 0.0625f;
    }
}

// ---------------------------------------------------------------------------
// Kernel: deformable PS-RoI pool of raw features -> output [N,8,7,7]
// ---------------------------------------------------------------------------
__global__ __launch_bounds__(256) void deform_pool_kernel(const float* __restrict__ f,
                                                          const float* __restrict__ rois,
                                                          float* __restrict__ out, int N)
{
    int idx = blockIdx.x * blockDim.x + threadIdx.x;
    if (idx >= N * KK * 8) return;
    int d   = idx & 7;
    int nb  = idx >> 3;
    int n   = nb / KK;
    int bin = nb - n * KK;
    int bi  = bin / KPOOL;
    int bj  = bin - bi * KPOOL;

    const float* r = rois + n * 5;
    float x1 = r[1] * 0.0625f;
    float y1 = r[2] * 0.0625f;
    float x2 = (r[3] + 1.0f) * 0.0625f;
    float y2 = (r[4] + 1.0f) * 0.0625f;
    float bw = (x2 - x1) / 7.0f;
    float bh = (y2 - y1) / 7.0f;
    float cx = x1 + ((float)bj + 0.5f) * bw;
    float cy = y1 + ((float)bi + 0.5f) * bh;

    int g = d >> 1;
    const float* o = g_off + (size_t)nb * 8 + g * 2;
    float sx = cx + o[0];
    float sy = cy + o[1];

    float y0f = floorf(sy), x0f = floorf(sx);
    float wy = sy - y0f,    wx = sx - x0f;
    int iy0 = min(max((int)y0f, 0), HH - 1);
    int iy1 = min(max((int)y0f + 1, 0), HH - 1);
    int ix0 = min(max((int)x0f, 0), WW - 1);
    int ix1 = min(max((int)x0f + 1, 0), WW - 1);

    int ch = bin * 8 + d;
    float v00 = __ldg(f + ((size_t)(iy0 * WW + ix0)) * CC + ch);
    float v01 = __ldg(f + ((size_t)(iy0 * WW + ix1)) * CC + ch);
    float v10 = __ldg(f + ((size_t)(iy1 * WW + ix0)) * CC + ch);
    float v11 = __ldg(f + ((size_t)(iy1 * WW + ix1)) * CC + ch);

    float val = (1.f - wy) * (1.f - wx) * v00 + (1.f - wy) * wx * v01
              + wy * (1.f - wx) * v10 + wy * wx * v11;

    out[((size_t)n * 8 + d) * KK + bin] = val;
}

// ---------------------------------------------------------------------------
extern "C" void kernel_launch(void* const* d_in, const int* in_sizes, int n_in,
                              void* d_out, int out_size)
{
    const float* features = (const float*)d_in[0];  // [1,128,128,392]
    const float* rois     = (const float*)d_in[1];  // [N,5]
    const float* conv_w   = (const float*)d_in[2];  // [3,3,392,392]
    float* out = (float*)d_out;
    int N = in_sizes[1] / 5;

    cudaFuncSetAttribute(conv_mma_kernel, cudaFuncAttributeMaxDynamicSharedMemorySize, SMEM_BYTES);

    {
        int tot = PFW * PFW * (CPAD / 4);
        pad_split_features<<<(tot + 255) / 256, 256>>>(features);
        dim3 gw(13, 13, 9);
        split_weights<<<gw, 256>>>(conv_w);
        int pt = CC * 9 * (CPAD - CC);
        pad_weights_tail<<<(pt + 255) / 256, 256>>>();
    }

    conv_mma_kernel<<<GRID, 256, SMEM_BYTES>>>();

    int t2 = N * KK;
    offset_pool_kernel<<<(t2 + 255) / 256, 256>>>(rois, N);

    int t3 = N * KK * 8;
    deform_pool_kernel<<<(t3 + 255) / 256, 256>>>(features, rois, out, N);
}